// round 14
// baseline (speedup 1.0000x reference)
#include <cuda_runtime.h>
#include <cuda_bf16.h>
#include <cstdint>
#include <math.h>

// Problem constants
#define SIZE_U   6000
#define SIZE_V   6000
#define N_TOTAL  12000
#define DIM      256
#define KTOP     20
#define ROW_LEN  12000
#define CAP      1024

#define OUT_X    0ull
#define OUT_US   36000000ull
#define OUT_VS   37536000ull

// int8 split scratch: row n in [0,12000) = concat(u_s, v_s)
__device__ signed char g_q1[(size_t)N_TOTAL * DIM];
__device__ signed char g_q2[(size_t)N_TOTAL * DIM];
__device__ float       g_scale[N_TOTAL];

// ---------------------------------------------------------------------------
// Kernel 1: per-row top-20, weighted merge, mask select, int8 split quant.
// Mask dtype detection inlined (block-uniform result from same 128 words).
// ---------------------------------------------------------------------------
__global__ __launch_bounds__(256)
void topk_merge_kernel(const float* __restrict__ u, const float* __restrict__ v,
                       const float* __restrict__ sim, const void* __restrict__ mask,
                       float* __restrict__ out)
{
    const int n   = blockIdx.x;
    const int tid = threadIdx.x;

    __shared__ float s_cval[CAP];
    __shared__ int   s_cidx[CAP];
    __shared__ int   s_cnt;
    __shared__ float s_rval[256];
    __shared__ int   s_ridx[256];
    __shared__ float s_selv[KTOP];
    __shared__ int   s_seli[KTOP];
    __shared__ float s_wsum;
    __shared__ int   s_word, s_bool;
    __shared__ float s_wmax[8];

    if (tid == 0) { s_word = 0; s_bool = 0; s_cnt = 0; }
    __syncthreads();
    // Inline mask dtype detection on the first 128 words (512B; in-bounds for
    // packed-bool (3000 words) and word-per-elem (12000 words) layouts).
    if (tid < 128) {
        unsigned w = ((const unsigned*)mask)[tid];
        if (w & 0xFEFEFEFEu)        atomicOr(&s_word, 1);   // some byte >= 2
        else if (w & 0xFFFFFF00u)   atomicOr(&s_bool, 1);   // bytes<=1, upper set
    }
    __syncthreads();
    const bool mask_is_bool = (s_bool && !s_word);

    bool keep;
    if (mask_is_bool) keep = ((const unsigned char*)mask)[n] != 0;
    else              keep = ((const unsigned*)mask)[n]      != 0;

    const float* feat = (n < SIZE_U) ? (u + (size_t)n * DIM)
                                     : (v + (size_t)(n - SIZE_U) * DIM);
    float* dst = (n < SIZE_U) ? (out + OUT_US + (size_t)n * DIM)
                              : (out + OUT_VS + (size_t)(n - SIZE_U) * DIM);

    float x;
    if (keep) {
        x = feat[tid];
    } else {
        const float T0 = 0.993f;
        const float4* row4 = (const float4*)(sim + (size_t)n * ROW_LEN);

        for (int i = tid; i < ROW_LEN / 4; i += 256) {
            float4 sv = row4[i];
            if (sv.x > T0) { int p = atomicAdd(&s_cnt, 1); if (p < CAP) { s_cval[p] = sv.x; s_cidx[p] = 4*i;   } }
            if (sv.y > T0) { int p = atomicAdd(&s_cnt, 1); if (p < CAP) { s_cval[p] = sv.y; s_cidx[p] = 4*i+1; } }
            if (sv.z > T0) { int p = atomicAdd(&s_cnt, 1); if (p < CAP) { s_cval[p] = sv.z; s_cidx[p] = 4*i+2; } }
            if (sv.w > T0) { int p = atomicAdd(&s_cnt, 1); if (p < CAP) { s_cval[p] = sv.w; s_cidx[p] = 4*i+3; } }
        }
        __syncthreads();
        const int cnt = s_cnt;

        if (cnt >= KTOP && cnt <= CAP) {
            // Single-pass rank selection.
            float myv[4]; int myi[4]; int myrank[4];
            int nown = 0;
            #pragma unroll
            for (int q = 0; q < 4; q++) {
                int c = tid + q * 256;
                if (c < cnt) { myv[q] = s_cval[c]; myi[q] = s_cidx[c]; myrank[q] = 0; nown = q + 1; }
            }
            if (nown > 0) {
                for (int j = 0; j < cnt; j++) {
                    float vj = s_cval[j]; int ij = s_cidx[j];
                    #pragma unroll
                    for (int q = 0; q < 4; q++) {
                        if (q < nown &&
                            (vj > myv[q] || (vj == myv[q] && ij < myi[q]))) myrank[q]++;
                    }
                }
                #pragma unroll
                for (int q = 0; q < 4; q++) {
                    if (q < nown && myrank[q] < KTOP) {
                        s_selv[myrank[q]] = myv[q];
                        s_seli[myrank[q]] = myi[q];
                    }
                }
            }
            __syncthreads();
        } else {
            // Slow path: 20 global argmax sweeps (pathological data / overflow).
            const float* row = sim + (size_t)n * ROW_LEN;
            for (int j = 0; j < KTOP; j++) {
                float bv = -3e38f; int bi = 0x7fffffff;
                for (int i = tid; i < ROW_LEN; i += 256) {
                    float vv = row[i];
                    bool used = false;
                    for (int q = 0; q < j; q++) if (s_seli[q] == i) used = true;
                    if (!used && (vv > bv || (vv == bv && i < bi))) { bv = vv; bi = i; }
                }
                s_rval[tid] = bv; s_ridx[tid] = bi;
                __syncthreads();
                for (int s = 128; s; s >>= 1) {
                    if (tid < s) {
                        float v2 = s_rval[tid + s]; int i2 = s_ridx[tid + s];
                        if (v2 > s_rval[tid] || (v2 == s_rval[tid] && i2 < s_ridx[tid])) {
                            s_rval[tid] = v2; s_ridx[tid] = i2;
                        }
                    }
                    __syncthreads();
                }
                if (tid == 0) { s_selv[j] = s_rval[0]; s_seli[j] = s_ridx[0]; }
                __syncthreads();
            }
        }

        if (tid == 0) {
            float s = 0.f;
            #pragma unroll
            for (int q = 0; q < KTOP; q++) s += s_selv[q];
            s_wsum = s;
        }
        __syncthreads();

        float acc = 0.f;
        #pragma unroll
        for (int q = 0; q < KTOP; q++) {
            int id = s_seli[q];
            const float* f = (id < SIZE_U) ? (u + (size_t)id * DIM)
                                           : (v + (size_t)(id - SIZE_U) * DIM);
            acc += s_selv[q] * f[tid];
        }
        x = acc / s_wsum;
    }

    dst[tid] = x;

    // ---- int8 split quantization (block-wide row max) ----
    float ax = fabsf(x);
    #pragma unroll
    for (int o = 16; o; o >>= 1) ax = fmaxf(ax, __shfl_xor_sync(0xffffffffu, ax, o));
    if ((tid & 31) == 0) s_wmax[tid >> 5] = ax;
    __syncthreads();
    float mx = s_wmax[0];
    #pragma unroll
    for (int w = 1; w < 8; w++) mx = fmaxf(mx, s_wmax[w]);

    float s1   = (mx > 0.f) ? mx * (1.f / 127.f) : 1.f;
    float inv1 = (mx > 0.f) ? 127.f / mx : 0.f;
    float q1 = rintf(x * inv1);                       // |q1| <= 127
    float r  = fmaf(-q1, s1, x);
    float q2 = rintf(r * inv1 * 256.f);
    q2 = fminf(fmaxf(q2, -127.f), 127.f);
    g_q1[(size_t)n * DIM + tid] = (signed char)(int)q1;
    g_q2[(size_t)n * DIM + tid] = (signed char)(int)q2;
    if (tid == 0) g_scale[n] = s1;
}

// ---------------------------------------------------------------------------
// Kernel 2: C = sigmoid(A @ B^T) via int8 split mma.m16n8k32 (2x MAC/instr
// vs bf16). x*y = sA*sB*(q1q1 + (q1q2 + q2q1)/256); q2q2/65536 dropped.
// CTA tile 128x128, 512 threads, 16 warps (4x4), warp tile 32x32.
// cp.async double-buffered, BK=64 bytes.
// ---------------------------------------------------------------------------
#define M6    6000
#define QBM   128
#define QBN   128
#define QBK   64
#define QNCH  (DIM / QBK)        // 4
#define QLD   80                 // smem row stride bytes (conflict-free LDSM)
#define QARR  (QBM * QLD)        // 10240
#define QSTG  (4 * QARR)         // 40960 per stage: [q1A|q2A|q1B|q2B]
#define SMEM_Q (2 * QSTG + 1024) // + scales

__device__ __forceinline__ unsigned ssa(const void* p) {
    return (unsigned)__cvta_generic_to_shared(p);
}
__device__ __forceinline__ void cp16(unsigned dst, const void* src, int bytes) {
    asm volatile("cp.async.cg.shared.global [%0], [%1], 16, %2;"
                 :: "r"(dst), "l"(src), "r"(bytes));
}
__device__ __forceinline__ void cp_commit() {
    asm volatile("cp.async.commit_group;" ::: "memory");
}
template <int N>
__device__ __forceinline__ void cp_wait() {
    asm volatile("cp.async.wait_group %0;" :: "n"(N) : "memory");
}
__device__ __forceinline__ void ldsm4(unsigned addr, unsigned& d0, unsigned& d1,
                                      unsigned& d2, unsigned& d3) {
    asm volatile("ldmatrix.sync.aligned.m8n8.x4.shared.b16 {%0,%1,%2,%3}, [%4];"
                 : "=r"(d0), "=r"(d1), "=r"(d2), "=r"(d3) : "r"(addr));
}
__device__ __forceinline__ void imma16832(int* c, const unsigned* a, unsigned b0, unsigned b1) {
    asm volatile(
        "mma.sync.aligned.m16n8k32.row.col.s32.s8.s8.s32 "
        "{%0,%1,%2,%3}, {%4,%5,%6,%7}, {%8,%9}, {%0,%1,%2,%3};"
        : "+r"(c[0]), "+r"(c[1]), "+r"(c[2]), "+r"(c[3])
        : "r"(a[0]), "r"(a[1]), "r"(a[2]), "r"(a[3]), "r"(b0), "r"(b1));
}

__global__ __launch_bounds__(512, 1)
void gemm_sigmoid_imma_kernel(float* __restrict__ C)
{
    extern __shared__ char smem[];
    const unsigned sb = ssa(smem);
    float* sSA = (float*)(smem + 2 * QSTG);
    float* sSB = sSA + 128;

    const int tid  = threadIdx.x;
    const int lane = tid & 31;
    const int wid  = tid >> 5;
    const int wr   = (wid >> 2) * 32;   // 0/32/64/96
    const int wc   = (wid & 3) * 32;    // 0/32/64/96
    const int row0 = blockIdx.y * QBM;
    const int col0 = blockIdx.x * QBN;

    int accM[2][4][4], accC[2][4][4];
    #pragma unroll
    for (int i = 0; i < 2; i++)
        #pragma unroll
        for (int j = 0; j < 4; j++)
            #pragma unroll
            for (int q = 0; q < 4; q++) { accM[i][j][q] = 0; accC[i][j][q] = 0; }

    auto load_stage = [&](int st, int kc) {
        const unsigned stbase = sb + st * QSTG;
        #pragma unroll
        for (int arr = 0; arr < 4; arr++) {
            const signed char* gsrc = (arr & 1) ? g_q2 : g_q1;
            const int rbase = (arr < 2) ? row0 : (SIZE_U + col0);
            const int rlim  = (arr < 2) ? (M6 - row0) : (M6 - col0);
            int row = tid >> 2;            // 0..127
            int c4  = tid & 3;             // 16B group within 64B
            const void* src = gsrc + (size_t)(rbase + row) * DIM + kc + c4 * 16;
            cp16(stbase + arr * QARR + row * QLD + c4 * 16, src,
                 (row < rlim) ? 16 : 0);
        }
        cp_commit();
    };

    // scales into smem
    if (tid < 128)       sSA[tid] = (row0 + tid < M6) ? g_scale[row0 + tid] : 1.f;
    else if (tid < 256)  { int r = tid - 128;
                           sSB[r] = (col0 + r < M6) ? g_scale[SIZE_U + col0 + r] : 1.f; }

    load_stage(0, 0);

    for (int c = 0; c < QNCH; c++) {
        const int st = c & 1;
        if (c + 1 < QNCH) load_stage(st ^ 1, (c + 1) * QBK);
        if (c + 1 < QNCH) cp_wait<1>(); else cp_wait<0>();
        __syncthreads();

        const char* sq1A = smem + st * QSTG;
        const char* sq2A = sq1A + QARR;
        const char* sq1B = sq1A + 2 * QARR;
        const char* sq2B = sq1A + 3 * QARR;

        #pragma unroll
        for (int ks = 0; ks < 2; ks++) {
            const int kb = ks * 32;       // byte offset of this k32 step
            unsigned a1[2][4], a2[2][4];
            {
                const int arow  = (lane & 15);
                const int abyte = kb + (lane & 16);      // ((lane&16)>>1) u16 = (lane&16) bytes
                #pragma unroll
                for (int mf = 0; mf < 2; mf++) {
                    int r = wr + mf * 16 + arow;
                    ldsm4(ssa(sq1A + r * QLD + abyte), a1[mf][0], a1[mf][1], a1[mf][2], a1[mf][3]);
                    ldsm4(ssa(sq2A + r * QLD + abyte), a2[mf][0], a2[mf][1], a2[mf][2], a2[mf][3]);
                }
            }
            unsigned b1[2][4], b2[2][4];
            {
                const int brow  = (lane & 7) + ((lane & 16) >> 1);
                const int bbyte = kb + (lane & 8) * 2;   // (lane&8) u16 = 2x bytes
                #pragma unroll
                for (int nh = 0; nh < 2; nh++) {
                    int r = wc + nh * 16 + brow;
                    ldsm4(ssa(sq1B + r * QLD + bbyte), b1[nh][0], b1[nh][1], b1[nh][2], b1[nh][3]);
                    ldsm4(ssa(sq2B + r * QLD + bbyte), b2[nh][0], b2[nh][1], b2[nh][2], b2[nh][3]);
                }
            }
            #pragma unroll
            for (int mf = 0; mf < 2; mf++)
                #pragma unroll
                for (int nf = 0; nf < 4; nf++) {
                    const int n2 = nf >> 1, h = (nf & 1) * 2;
                    imma16832(accM[mf][nf], a1[mf], b1[n2][h], b1[n2][h + 1]);
                    imma16832(accC[mf][nf], a1[mf], b2[n2][h], b2[n2][h + 1]);
                    imma16832(accC[mf][nf], a2[mf], b1[n2][h], b1[n2][h + 1]);
                }
        }
        __syncthreads();
    }

    // Epilogue: x = sA*sB*(accM + accC/256); sigmoid; store.
    const int g = lane >> 2, t = lane & 3;
    #pragma unroll
    for (int mf = 0; mf < 2; mf++) {
        const int lr0 = wr + mf * 16 + g;
        const float sa0 = sSA[lr0], sa1 = sSA[lr0 + 8];
        const int r0 = row0 + lr0;
        #pragma unroll
        for (int nf = 0; nf < 4; nf++) {
            const int lc = wc + nf * 8 + t * 2;
            const int cc = col0 + lc;
            if (cc >= M6) continue;
            const float sb0 = sSB[lc], sb1 = sSB[lc + 1];
            if (r0 < M6) {
                float x0 = sa0 * sb0 * ((float)accM[mf][nf][0] + (float)accC[mf][nf][0] * (1.f / 256.f));
                float x1 = sa0 * sb1 * ((float)accM[mf][nf][1] + (float)accC[mf][nf][1] * (1.f / 256.f));
                float2 o;
                o.x = __fdividef(1.f, 1.f + __expf(-x0));
                o.y = __fdividef(1.f, 1.f + __expf(-x1));
                *(float2*)(C + (size_t)r0 * M6 + cc) = o;
            }
            const int r1 = r0 + 8;
            if (r1 < M6) {
                float x2 = sa1 * sb0 * ((float)accM[mf][nf][2] + (float)accC[mf][nf][2] * (1.f / 256.f));
                float x3 = sa1 * sb1 * ((float)accM[mf][nf][3] + (float)accC[mf][nf][3] * (1.f / 256.f));
                float2 o;
                o.x = __fdividef(1.f, 1.f + __expf(-x2));
                o.y = __fdividef(1.f, 1.f + __expf(-x3));
                *(float2*)(C + (size_t)r1 * M6 + cc) = o;
            }
        }
    }
}

// ---------------------------------------------------------------------------
extern "C" void kernel_launch(void* const* d_in, const int* in_sizes, int n_in,
                              void* d_out, int out_size)
{
    const float* u   = (const float*)d_in[0];
    const float* v   = (const float*)d_in[1];
    const float* sim = (const float*)d_in[2];
    const void*  msk = d_in[3];
    float* out = (float*)d_out;

    topk_merge_kernel<<<N_TOTAL, 256>>>(u, v, sim, msk, out);

    cudaFuncSetAttribute(gemm_sigmoid_imma_kernel,
                         cudaFuncAttributeMaxDynamicSharedMemorySize, SMEM_Q);
    dim3 g((M6 + QBN - 1) / QBN, (M6 + QBM - 1) / QBM);
    gemm_sigmoid_imma_kernel<<<g, 512, SMEM_Q>>>(out + OUT_X);
}